// round 8
// baseline (speedup 1.0000x reference)
#include <cuda_runtime.h>
#include <cstdint>

#define KMIX 64
#define DDIM 16
#define KS2C 0x1BD11BF0u   // 0x1BD11BDA ^ 0 ^ 42
#define NLN2 (-0.69314718055994530942f)
#define TINY 1.17549435e-38f
#define VBIAS 32.0f

__device__ __align__(16) float g_logpb[KMIX];  // log(p) + VBIAS (pre-biased)
__device__ float4 g_Ltt4[KMIX * 64];   // [z][c(4)][p(16)] -> Ltt[z][c][p].j = L[z][4c+j][p]
// mutable constants: {2^15, 2^29, 2^6, 1, 2^23} — loaded at runtime so ptxas
// cannot strength-reduce the IMADs back into shifts / fold the add.
__device__ uint32_t g_c[5] = {1u << 15, 1u << 29, 1u << 6, 1u, 1u << 23};

// --- prep: biased logits + L transpose to [z][c][p][j] float4 layout ---------
__global__ void prep_kernel(const float* __restrict__ pi,
                            const float* __restrict__ Ls) {
    int z = blockIdx.x, t = threadIdx.x;
    int c = t >> 6, rem = t & 63, p = rem >> 2, j = rem & 3;
    ((float*)g_Ltt4)[z * 256 + c * 64 + p * 4 + j] = Ls[z * 256 + (4 * c + j) * 16 + p];
    if (z == 0 && t < KMIX) {
        float acc = 0.0f;
        for (int q = 0; q < KMIX; q++) acc += pi[q];
        g_logpb[t] = logf(pi[t] / acc) + VBIAS;
    }
}

// A-round: add on fma pipe (IMAD via runtime 'one'), rotate = SHF (alu), xor = LOP3
__device__ __forceinline__ void tfA(uint32_t& x0, uint32_t& x1, int r, uint32_t one) {
    x0 = x1 * one + x0;
    x1 = __funnelshift_l(x1, x1, r) ^ x0;
}
// B-round: add + rotate all on fma pipe (IMAD, IMAD, IMAD.HI), xor = LOP3 (alu)
__device__ __forceinline__ void tfB(uint32_t& x0, uint32_t& x1, uint32_t m, uint32_t one) {
    x0 = x1 * one + x0;
    uint32_t lo = x1 * m;
    uint32_t hi = __umulhi(x1, m);
    x1 = (lo | hi) ^ x0;
}
// injection round (A-style): x1+=B on fma (IMAD imm), x0=x0+x1+A one IADD3
__device__ __forceinline__ void tfAinj(uint32_t& x0, uint32_t& x1,
                                       uint32_t A, uint32_t B, int r, uint32_t one) {
    x1 = x1 * one + B;
    x0 = x0 + x1 + A;
    x1 = __funnelshift_l(x1, x1, r) ^ x0;
}

// threefry2x32(key=(0,42), ctr=(0,i)), 20 rounds; bits = out0 ^ out1
__device__ __forceinline__ uint32_t rng_bits(uint32_t i, uint32_t m15, uint32_t m29,
                                             uint32_t m6, uint32_t one) {
    uint32_t x1 = i + 42u;
    uint32_t x0 = x1;                       // round 1 (x0 was 0): x0 += x1
    x1 = __funnelshift_l(x1, x1, 13) ^ x0;  //   rotate/xor of round 1
    tfB(x0, x1, m15, one);
    tfA(x0, x1, 26, one);
    tfB(x0, x1, m6, one);
    tfAinj(x0, x1, 42u, KS2C + 1u, 17, one);
    tfB(x0, x1, m29, one);
    tfA(x0, x1, 16, one);
    tfA(x0, x1, 24, one);
    tfAinj(x0, x1, KS2C, 2u, 13, one);
    tfB(x0, x1, m15, one);
    tfA(x0, x1, 26, one);
    tfB(x0, x1, m6, one);
    tfAinj(x0, x1, 0u, 45u, 17, one);
    tfB(x0, x1, m29, one);
    tfA(x0, x1, 16, one);
    tfA(x0, x1, 24, one);
    tfAinj(x0, x1, 42u, KS2C + 4u, 13, one);
    tfB(x0, x1, m15, one);
    tfA(x0, x1, 26, one);
    tfA(x0, x1, 6, one);
    return (x0 + KS2C) ^ (x1 + 5u);
}

__device__ __forceinline__ float gumbel_exact(float u) {
    return -logf(-logf(u));   // accurate libdevice path (matches XLA)
}

// ----------------------------------------------------------------------------
// 1 warp = 2 samples. lanes 0..15 -> sample A, lanes 16..31 -> sample B.
// lane (g,p) owns components 4p..4p+3 of its sample.
// ----------------------------------------------------------------------------
__global__ __launch_bounds__(256, 6)
void gmm_sample_kernel(const float* __restrict__ x,
                       const float* __restrict__ means,
                       float* __restrict__ y,
                       int nPairs) {
    __shared__ float4 s_x4[8][8];          // [warpInBlock][2 samples x 4 chunks]

    uint32_t m15 = g_c[0], m29 = g_c[1], m6 = g_c[2], one = g_c[3], m23 = g_c[4];

    int warp = (blockIdx.x * blockDim.x + threadIdx.x) >> 5;
    int lane = threadIdx.x & 31;
    int wib  = (threadIdx.x >> 5);
    if (warp >= nPairs) return;

    int p = lane & 15;
    int g = lane >> 4;
    int n = 2 * warp + g;
    int kbase = 4 * p;
    uint32_t hmask = g ? 0xFFFF0000u : 0x0000FFFFu;

    float4 cvb = __ldg(&((const float4*)g_logpb)[p]);   // logp + 32

    uint32_t ibase = (uint32_t)n * KMIX + (uint32_t)kbase;
    uint32_t b0 = rng_bits(ibase + 0u, m15, m29, m6, one);
    uint32_t b1 = rng_bits(ibase + 1u, m15, m29, m6, one);
    uint32_t b2 = rng_bits(ibase + 2u, m15, m29, m6, one);
    uint32_t b3 = rng_bits(ibase + 3u, m15, m29, m6, one);

    // bits -> uniform [tiny,1): b>>9 done as umulhi(b, 2^23) on the fma pipe
    float u0 = fmaxf(__uint_as_float(__umulhi(b0, m23) | 0x3f800000u) - 1.0f, TINY);
    float u1 = fmaxf(__uint_as_float(__umulhi(b1, m23) | 0x3f800000u) - 1.0f, TINY);
    float u2 = fmaxf(__uint_as_float(__umulhi(b2, m23) | 0x3f800000u) - 1.0f, TINY);
    float u3 = fmaxf(__uint_as_float(__umulhi(b3, m23) | 0x3f800000u) - 1.0f, TINY);

    float t0 = __log2f(u0) * NLN2;         // = -ln(u) > 0
    float t1 = __log2f(u1) * NLN2;
    float t2 = __log2f(u2) * NLN2;
    float t3 = __log2f(u3) * NLN2;

    // biased gumbel+logit: strictly positive (range ~ (20.8, 48.6))
    float v0 = fmaf(__log2f(t0), NLN2, cvb.x);
    float v1 = fmaf(__log2f(t1), NLN2, cvb.y);
    float v2 = fmaf(__log2f(t2), NLN2, cvb.z);
    float v3 = fmaf(__log2f(t3), NLN2, cvb.w);

    // positive floats order as uints: pack (63-k) into low 6 bits (one LOP3 each)
    uint32_t pk0 = (__float_as_uint(v0) & 0xFFFFFFC0u) | (uint32_t)(63 - kbase);
    uint32_t pk1 = (__float_as_uint(v1) & 0xFFFFFFC0u) | (uint32_t)(62 - kbase);
    uint32_t pk2 = (__float_as_uint(v2) & 0xFFFFFFC0u) | (uint32_t)(61 - kbase);
    uint32_t pk3 = (__float_as_uint(v3) & 0xFFFFFFC0u) | (uint32_t)(60 - kbase);

    // local top-2 of 4 (pure IMNMX)
    uint32_t a  = max(pk0, pk1), bq = min(pk0, pk1);
    uint32_t cq = max(pk2, pk3), dq = min(pk2, pk3);
    uint32_t lm1 = max(a, cq);
    uint32_t lm2 = max(min(a, cq), max(bq, dq));
    float tl = fminf(fminf(t0, t1), fminf(t2, t3));

    // half-warp reductions via redux.sync (single-instruction warp collectives)
    uint32_t w1 = __reduce_max_sync(hmask, lm1);
    uint32_t s  = (lm1 == w1) ? lm2 : lm1;       // my best candidate for 2nd place
    uint32_t w2 = __reduce_max_sync(hmask, s);
    uint32_t tm = __reduce_min_sync(hmask, __float_as_uint(tl));  // t>0: uint order ok
    float tmin = __uint_as_float(tm);

    int z = 63 - (int)(w1 & 63u);

    // threshold: fast-log err (1e-6/t blowup + relative on |g|=|v-32|) + 64-ulp
    // packing/masking slack at magnitude ~48 (2.4e-4, 2.5x safety -> 6e-4)
    float v1f = __uint_as_float(w1 & 0xFFFFFFC0u);
    float v2f = __uint_as_float(w2 & 0xFFFFFFC0u);
    float thr = __fdividef(1e-6f, tmin)
              + 6e-5f * fmaxf(1.0f, fabsf(v1f - VBIAS)) + 6e-4f;
    bool need = (v1f - v2f) <= thr;

    if (__any_sync(0xffffffffu, need)) {   // rare exact recompute (~1e-3 of warps)
        float e0 = gumbel_exact(u0) + (cvb.x - VBIAS);
        float e1 = gumbel_exact(u1) + (cvb.y - VBIAS);
        float e2 = gumbel_exact(u2) + (cvb.z - VBIAS);
        float e3 = gumbel_exact(u3) + (cvb.w - VBIAS);
        float av; int ai;
        if (e0 >= e1) { av = e0; ai = kbase; } else { av = e1; ai = kbase + 1; }
        if (e2 > av) { av = e2; ai = kbase + 2; }
        if (e3 > av) { av = e3; ai = kbase + 3; }
#pragma unroll
        for (int o = 1; o < 16; o <<= 1) {
            float ov = __shfl_xor_sync(0xffffffffu, av, o);
            int   oi = __shfl_xor_sync(0xffffffffu, ai, o);
            if (ov > av || (ov == av && oi < ai)) { av = ov; ai = oi; }
        }
        if (need) z = ai;
    }

    // matvec via smem x-broadcast + transposed-L float4 loads:
    //   y[n][p] = means[z][p] + sum_c dot(x[n][4c..4c+3], Ltt[z][c][p])
    float xv = x[(size_t)n * DDIM + p];
    ((float*)&s_x4[wib][0])[lane] = xv;
    __syncwarp();

    float acc = __ldg(&means[z * DDIM + p]);
    const float4* Lt = &g_Ltt4[z * 64 + p];
    const float4* sx = &s_x4[wib][g * 4];
#pragma unroll
    for (int c = 0; c < 4; c++) {
        float4 xc = sx[c];                 // broadcast LDS.128
        float4 lc = __ldg(&Lt[c * 16]);    // coalesced LDG.128 (L1/L2-resident table)
        acc = fmaf(xc.x, lc.x, acc);
        acc = fmaf(xc.y, lc.y, acc);
        acc = fmaf(xc.z, lc.z, acc);
        acc = fmaf(xc.w, lc.w, acc);
    }
    y[(size_t)n * DDIM + p] = acc;
}

// ----------------------------------------------------------------------------
extern "C" void kernel_launch(void* const* d_in, const int* in_sizes, int n_in,
                              void* d_out, int out_size) {
    const float* x     = (const float*)d_in[0];   // (N, 16)
    const float* pi    = (const float*)d_in[1];   // (64,)
    const float* means = (const float*)d_in[2];   // (64, 16)
    const float* Ls    = (const float*)d_in[3];   // (64, 16, 16)
    float* y = (float*)d_out;                     // (N, 16)

    int N = in_sizes[0] / DDIM;
    int nPairs = N / 2;                           // N = 1,000,000 (even)

    prep_kernel<<<KMIX, 256>>>(pi, Ls);

    const int threads = 256;                      // 8 warps = 16 samples / CTA
    int warpsPerBlock = threads / 32;
    int blocks = (nPairs + warpsPerBlock - 1) / warpsPerBlock;
    gmm_sample_kernel<<<blocks, threads>>>(x, means, y, nPairs);
}

// round 9
// speedup vs baseline: 1.1500x; 1.1500x over previous
#include <cuda_runtime.h>
#include <cstdint>

#define KMIX 64
#define DDIM 16
#define KS2C 0x1BD11BF0u   // 0x1BD11BDA ^ 0 ^ 42
#define NLN2 (-0.69314718055994530942f)
#define TINY 1.17549435e-38f
#define VBIAS 32.0f

__device__ __align__(16) float g_logp[KMIX];    // exact log(p)  (slow path)
__device__ __align__(16) float g_logpb[KMIX];   // log(p)+VBIAS  (fast path)
__device__ float4 g_Ltt4[KMIX * 64];  // [z][c(4)][p(16)]: .j = L[z][4c+j][p]

// --- prep: logits (both copies) + transposed L table -------------------------
__global__ void prep_kernel(const float* __restrict__ pi,
                            const float* __restrict__ Ls) {
    int z = blockIdx.x, t = threadIdx.x;
    int c = t >> 6, rem = t & 63, p = rem >> 2, j = rem & 3;
    ((float*)g_Ltt4)[z * 256 + c * 64 + p * 4 + j] = Ls[z * 256 + (4 * c + j) * 16 + p];
    if (z == 0 && t < KMIX) {
        float acc = 0.0f;
        for (int q = 0; q < KMIX; q++) acc += pi[q];
        float lp = logf(pi[t] / acc);
        g_logp[t]  = lp;
        g_logpb[t] = lp + VBIAS;
    }
}

// --- threefry2x32, 20 rounds, key=(0,42); simple SHF rounds (best measured) --
__device__ __forceinline__ uint2 threefry2x32(uint32_t x0, uint32_t x1) {
    const uint32_t ks1 = 42u;
    x0 += 0u; x1 += ks1;
#define TF_R(r) { x0 += x1; x1 = __funnelshift_l(x1, x1, (r)); x1 ^= x0; }
    TF_R(13) TF_R(15) TF_R(26) TF_R(6)
    x0 += ks1; x1 += KS2C + 1u;
    TF_R(17) TF_R(29) TF_R(16) TF_R(24)
    x0 += KS2C; x1 += 0u + 2u;
    TF_R(13) TF_R(15) TF_R(26) TF_R(6)
    x0 += 0u; x1 += ks1 + 3u;
    TF_R(17) TF_R(29) TF_R(16) TF_R(24)
    x0 += ks1; x1 += KS2C + 4u;
    TF_R(13) TF_R(15) TF_R(26) TF_R(6)
    x0 += KS2C; x1 += 0u + 5u;
#undef TF_R
    return make_uint2(x0, x1);
}
__device__ __forceinline__ uint32_t rng_bits(uint32_t i) {
    uint2 r = threefry2x32(0u, i);
    return r.x ^ r.y;
}

__device__ __forceinline__ float gumbel_exact(float u) {
    return -logf(-logf(u));   // accurate libdevice path (matches XLA)
}

// ----------------------------------------------------------------------------
// 1 warp = 2 samples. lanes 0..15 -> sample A, lanes 16..31 -> sample B.
// lane (g,p) owns components 4p..4p+3 of its sample.
// ----------------------------------------------------------------------------
__global__ __launch_bounds__(256, 8)
void gmm_sample_kernel(const float* __restrict__ x,
                       const float* __restrict__ means,
                       float* __restrict__ y,
                       int nPairs) {
    __shared__ float4 s_x4[8][8];          // [warpInBlock][2 samples x 4 chunks]

    int warp = (blockIdx.x * blockDim.x + threadIdx.x) >> 5;
    int lane = threadIdx.x & 31;
    int wib  = (threadIdx.x >> 5);
    if (warp >= nPairs) return;

    int p = lane & 15;
    int g = lane >> 4;
    int n = 2 * warp + g;
    int kbase = 4 * p;

    float4 cvb = __ldg(&((const float4*)g_logpb)[p]);   // logp + 32

    uint32_t ibase = (uint32_t)n * KMIX + (uint32_t)kbase;
    uint32_t b0 = rng_bits(ibase + 0u);
    uint32_t b1 = rng_bits(ibase + 1u);
    uint32_t b2 = rng_bits(ibase + 2u);
    uint32_t b3 = rng_bits(ibase + 3u);

    // bits -> uniform [tiny,1)
    float u0 = fmaxf(__uint_as_float((b0 >> 9) | 0x3f800000u) - 1.0f, TINY);
    float u1 = fmaxf(__uint_as_float((b1 >> 9) | 0x3f800000u) - 1.0f, TINY);
    float u2 = fmaxf(__uint_as_float((b2 >> 9) | 0x3f800000u) - 1.0f, TINY);
    float u3 = fmaxf(__uint_as_float((b3 >> 9) | 0x3f800000u) - 1.0f, TINY);

    float t0 = __log2f(u0) * NLN2;         // = -ln(u) > 0
    float t1 = __log2f(u1) * NLN2;
    float t2 = __log2f(u2) * NLN2;
    float t3 = __log2f(u3) * NLN2;

    // biased gumbel+logit: strictly positive (range ~ [21.6, 44.3])
    float v0 = fmaf(__log2f(t0), NLN2, cvb.x);
    float v1 = fmaf(__log2f(t1), NLN2, cvb.y);
    float v2 = fmaf(__log2f(t2), NLN2, cvb.z);
    float v3 = fmaf(__log2f(t3), NLN2, cvb.w);

    // positive floats order as uints: pack (63-k) into low 6 bits (one LOP3 each)
    uint32_t pk0 = (__float_as_uint(v0) & 0xFFFFFFC0u) | (uint32_t)(63 - kbase);
    uint32_t pk1 = (__float_as_uint(v1) & 0xFFFFFFC0u) | (uint32_t)(62 - kbase);
    uint32_t pk2 = (__float_as_uint(v2) & 0xFFFFFFC0u) | (uint32_t)(61 - kbase);
    uint32_t pk3 = (__float_as_uint(v3) & 0xFFFFFFC0u) | (uint32_t)(60 - kbase);

    // local top-2 of 4 (pure IMNMX) + local tmin
    uint32_t a  = max(pk0, pk1), bq = min(pk0, pk1);
    uint32_t cq = max(pk2, pk3), dq = min(pk2, pk3);
    uint32_t w1 = max(a, cq);
    uint32_t w2 = max(min(a, cq), max(bq, dq));
    float tl = fminf(fminf(t0, t1), fminf(t2, t3));
    uint32_t tm = __float_as_uint(tl);     // t > 0: float order == uint order

    // 16-lane butterfly top-2 + tmin (both samples reduce in the same instrs)
#pragma unroll
    for (int o = 1; o < 16; o <<= 1) {
        uint32_t o1 = __shfl_xor_sync(0xffffffffu, w1, o);
        uint32_t o2 = __shfl_xor_sync(0xffffffffu, w2, o);
        uint32_t ot = __shfl_xor_sync(0xffffffffu, tm, o);
        w2 = max(min(w1, o1), max(w2, o2));
        w1 = max(w1, o1);
        tm = min(tm, ot);
    }
    int z = 63 - (int)(w1 & 63u);
    float tmin = __uint_as_float(tm);

    // threshold: fast-log err (1e-6/t blowup + relative on |g|) + masking slack
    // (2 x 64 ulp at |v|<64 = 4.9e-4, plus logit rounding; 8e-4 keeps >1.6x slack)
    float v1f = __uint_as_float(w1 & 0xFFFFFFC0u);
    float v2f = __uint_as_float(w2 & 0xFFFFFFC0u);
    float thr = __fdividef(1e-6f, tmin)
              + 6e-5f * fmaxf(1.0f, fabsf(v1f - VBIAS)) + 8e-4f;
    bool need = (v1f - v2f) <= thr;

    if (__any_sync(0xffffffffu, need)) {   // rare exact recompute (~2e-3 of warps)
        float4 cv = __ldg(&((const float4*)g_logp)[p]);   // exact logits
        float e0 = gumbel_exact(u0) + cv.x;
        float e1 = gumbel_exact(u1) + cv.y;
        float e2 = gumbel_exact(u2) + cv.z;
        float e3 = gumbel_exact(u3) + cv.w;
        float av; int ai;
        if (e0 >= e1) { av = e0; ai = kbase; } else { av = e1; ai = kbase + 1; }
        if (e2 > av) { av = e2; ai = kbase + 2; }
        if (e3 > av) { av = e3; ai = kbase + 3; }
#pragma unroll
        for (int o = 1; o < 16; o <<= 1) {
            float ov = __shfl_xor_sync(0xffffffffu, av, o);
            int   oi = __shfl_xor_sync(0xffffffffu, ai, o);
            if (ov > av || (ov == av && oi < ai)) { av = ov; ai = oi; }
        }
        if (need) z = ai;
    }

    // matvec via smem x-broadcast + transposed-L float4 loads:
    //   y[n][p] = means[z][p] + sum_c dot(x[n][4c..4c+3], Ltt[z][c][p])
    float xv = x[(size_t)n * DDIM + p];
    ((float*)&s_x4[wib][0])[lane] = xv;
    __syncwarp();

    float acc = __ldg(&means[z * DDIM + p]);
    const float4* Lt = &g_Ltt4[z * 64 + p];
    const float4* sx = &s_x4[wib][g * 4];
#pragma unroll
    for (int c = 0; c < 4; c++) {
        float4 xc = sx[c];                 // broadcast LDS.128
        float4 lc = __ldg(&Lt[c * 16]);    // coalesced LDG.128 (L2-resident table)
        acc = fmaf(xc.x, lc.x, acc);
        acc = fmaf(xc.y, lc.y, acc);
        acc = fmaf(xc.z, lc.z, acc);
        acc = fmaf(xc.w, lc.w, acc);
    }
    y[(size_t)n * DDIM + p] = acc;
}

// ----------------------------------------------------------------------------
extern "C" void kernel_launch(void* const* d_in, const int* in_sizes, int n_in,
                              void* d_out, int out_size) {
    const float* x     = (const float*)d_in[0];   // (N, 16)
    const float* pi    = (const float*)d_in[1];   // (64,)
    const float* means = (const float*)d_in[2];   // (64, 16)
    const float* Ls    = (const float*)d_in[3];   // (64, 16, 16)
    float* y = (float*)d_out;                     // (N, 16)

    int N = in_sizes[0] / DDIM;
    int nPairs = N / 2;                           // N = 1,000,000 (even)

    prep_kernel<<<KMIX, 256>>>(pi, Ls);

    const int threads = 256;                      // 8 warps = 16 samples / CTA
    int warpsPerBlock = threads / 32;
    int blocks = (nPairs + warpsPerBlock - 1) / warpsPerBlock;
    gmm_sample_kernel<<<blocks, threads>>>(x, means, y, nPairs);
}